// round 5
// baseline (speedup 1.0000x reference)
#include <cuda_runtime.h>
#include <cuda_bf16.h>
#include <cstdint>

#define NIMG 8
#define NA   3
#define HH   100
#define WW   100
#define NHW  10000
#define NANC 30000          // H*W*A
#define PRE  2000
#define PREP 2048           // padded to pow2 for bitonic sort
#define POST 1000
#define NWRD 32             // ceil(2000/64) mask words per row
#define IMGW 1600.0f
#define BBOX_CLIP 4.135166556742356f   // log(1000/16)
#define NMS_THR 0.7f
#define PFD  16             // prefetch depth in kernel C

// ---------------- device-global scratch (no runtime allocation) ----------------
__device__ unsigned int       g_sb[NIMG][NANC];            // sigmoid score bits, anchor order
__device__ float4             g_boxes[NIMG][PRE];
__device__ float              g_scores[NIMG][PRE];
__device__ unsigned char      g_valid[NIMG][PREP];         // padded: lanes read 64B each
__device__ unsigned long long g_mask[NIMG][PRE][NWRD];     // ~4.1 MB

// =============================================================================
// Kernel 0: full-chip sigmoid + layout transform (N,A,H,W) -> [img][hw*3+a]
// =============================================================================
__global__ __launch_bounds__(256)
void sigmoid_kernel(const float* __restrict__ obj_all)
{
    int gid = blockIdx.x * 256 + threadIdx.x;
    if (gid >= NIMG * NANC) return;
    int img = gid / NANC;
    int r   = gid - img * NANC;      // r = a*NHW + hw  (input memory order -> coalesced read)
    int a   = r / NHW;
    int hw  = r - a * NHW;
    float o = obj_all[gid];
    float s = 1.0f / (1.0f + expf(-o));
    g_sb[img][hw * NA + a] = __float_as_uint(s);   // scores in (0,1): bits monotonic
}

// =============================================================================
// Kernel A: radix-select threshold -> compact -> bitonic sort -> decode/clip.
// One block (1024 thr) per image.
// =============================================================================
__global__ __launch_bounds__(1024)
void topk_decode_kernel(const float* __restrict__ reg_all,
                        const float* __restrict__ anc_all)
{
    extern __shared__ unsigned char smem_raw[];
    unsigned int*       s_sb   = (unsigned int*)smem_raw;                  // 30000 u32
    unsigned long long* s_keys = (unsigned long long*)(smem_raw + 120000); // 2048 u64

    __shared__ unsigned int s_hist[256];
    __shared__ unsigned int s_scan[256];
    __shared__ unsigned int s_cnt;
    __shared__ unsigned int s_prefix;
    __shared__ int          s_K;

    const int img = blockIdx.x;
    const int tid = threadIdx.x;

    // ---- phase 1: coalesced vector copy of score bits into smem ----
    {
        const uint4* src = (const uint4*)g_sb[img];          // 7500 uint4
        uint4* dst = (uint4*)s_sb;
        for (int i = tid; i < NANC / 4; i += 1024) dst[i] = src[i];
    }
    if (tid == 0) { s_prefix = 0; s_K = PRE; }
    __syncthreads();

    // ---- phase 2: 4-pass MSB radix select for the PRE-th largest value ----
    unsigned int pmask = 0;
    for (int pass = 0; pass < 4; ++pass) {
        int shift = 24 - 8 * pass;
        if (tid < 256) s_hist[tid] = 0;
        __syncthreads();
        unsigned int prefix = s_prefix;
        for (int i = tid; i < NANC; i += 1024) {
            unsigned int v = s_sb[i];
            if ((v & pmask) == prefix)
                atomicAdd(&s_hist[(v >> shift) & 255u], 1u);
        }
        __syncthreads();
        // parallel inclusive suffix-sum over 256 bins
        if (tid < 256) s_scan[tid] = s_hist[tid];
        __syncthreads();
        for (int off = 1; off < 256; off <<= 1) {
            unsigned int add = 0;
            if (tid < 256) add = (tid + off < 256) ? s_scan[tid + off] : 0u;
            __syncthreads();
            if (tid < 256) s_scan[tid] += add;
            __syncthreads();
        }
        int Kc = s_K;
        __syncthreads();
        if (tid < 256) {
            unsigned int cs  = s_scan[tid];
            unsigned int nxt = (tid < 255) ? s_scan[tid + 1] : 0u;
            if ((int)cs >= Kc && (int)nxt < Kc) {
                s_K = Kc - (int)nxt;                       // remaining within this bin
                s_prefix = s_prefix | ((unsigned int)tid << shift);
            }
        }
        pmask |= (0xFFu << shift);
        __syncthreads();
    }
    const unsigned int T = s_prefix;   // exact bits of the PRE-th largest score

    // ---- phase 3: compact candidates >= T ----
    if (tid == 0) s_cnt = 0;
    __syncthreads();
    for (int i = tid; i < NANC; i += 1024) {
        unsigned int v = s_sb[i];
        if (v >= T) {
            unsigned int pos = atomicAdd(&s_cnt, 1u);
            if (pos < PREP)
                s_keys[pos] = ((unsigned long long)v << 32) |
                              (unsigned long long)(~(unsigned int)i);
        }
    }
    __syncthreads();
    unsigned int n = s_cnt; if (n > PREP) n = PREP;
    for (int i = tid; i < PREP; i += 1024)
        if (i >= (int)n) s_keys[i] = 0ULL;
    __syncthreads();

    // ---- phase 4: bitonic sort (descending) of 2048 keys ----
    for (int k = 2; k <= PREP; k <<= 1) {
        for (int j = k >> 1; j > 0; j >>= 1) {
            for (int i = tid; i < PREP; i += 1024) {
                int l = i ^ j;
                if (l > i) {
                    unsigned long long a = s_keys[i];
                    unsigned long long b = s_keys[l];
                    bool up = ((i & k) == 0);
                    if ((a < b) == up) { s_keys[i] = b; s_keys[l] = a; }
                }
            }
            __syncthreads();
        }
    }

    // ---- phase 5: decode / clip / validity for top PRE ----
    const float* reg = reg_all + (size_t)img * NA * 4 * NHW;
    const float4* anc = (const float4*)anc_all + (size_t)img * NANC;
    for (int j = tid; j < PRE; j += 1024) {
        unsigned long long key = s_keys[j];
        unsigned int idx = ~(unsigned int)(key & 0xFFFFFFFFull);
        float score = __uint_as_float((unsigned int)(key >> 32));

        int hw = idx / NA;
        int a  = idx - hw * NA;
        const float* rb = reg + (a * 4) * NHW + hw;
        float dx = rb[0];
        float dy = rb[NHW];
        float dw = rb[2 * NHW];
        float dh = rb[3 * NHW];
        dw = fminf(dw, BBOX_CLIP);
        dh = fminf(dh, BBOX_CLIP);

        float4 A4 = anc[idx];
        float w  = A4.z - A4.x + 1.0f;
        float h  = A4.w - A4.y + 1.0f;
        float cx = A4.x + 0.5f * w;
        float cy = A4.y + 0.5f * h;

        float pcx = dx * w + cx;
        float pcy = dy * h + cy;
        float pw  = expf(dw) * w;
        float ph  = expf(dh) * h;

        float x1 = pcx - 0.5f * pw;
        float y1 = pcy - 0.5f * ph;
        float x2 = pcx + 0.5f * pw - 1.0f;
        float y2 = pcy + 0.5f * ph - 1.0f;

        x1 = fminf(fmaxf(x1, 0.0f), IMGW - 1.0f);
        x2 = fminf(fmaxf(x2, 0.0f), IMGW - 1.0f);
        y1 = fminf(fmaxf(y1, 0.0f), IMGW - 1.0f);
        y2 = fminf(fmaxf(y2, 0.0f), IMGW - 1.0f);

        float ws = x2 - x1 + 1.0f;
        float hs = y2 - y1 + 1.0f;
        float xc = x1 + ws * 0.5f;
        float yc = y1 + hs * 0.5f;
        unsigned char v = (ws >= 0.0f) & (hs >= 0.0f) & (xc < IMGW) & (yc < IMGW);

        g_boxes[img][j]  = make_float4(x1, y1, x2, y2);
        g_scores[img][j] = score;
        g_valid[img][j]  = v;
    }
    // zero the pad bytes so kernel C's packed reads are well-defined
    for (int j = PRE + tid; j < PREP; j += 1024) g_valid[img][j] = 0;
}

// =============================================================================
// Kernel B: NMS suppression bitmask. grid (colBlk=32, rowQuad=8, img=8), 256 thr
// =============================================================================
__global__ __launch_bounds__(256)
void nms_mask_kernel()
{
    const int img    = blockIdx.z;
    const int colBlk = blockIdx.x;
    const int row    = blockIdx.y * 256 + threadIdx.x;

    __shared__ float4 s_col[64];
    const int colBase = colBlk * 64;
    if (threadIdx.x < 64) {
        int c = colBase + threadIdx.x;
        if (c < PRE) s_col[threadIdx.x] = g_boxes[img][c];
    }
    __syncthreads();

    if (row >= PRE) return;
    if (colBlk < (row >> 6)) {             // tile entirely below diagonal
        g_mask[img][row][colBlk] = 0ULL;
        return;
    }

    float4 rb = g_boxes[img][row];
    float rArea = (rb.z - rb.x + 1.0f) * (rb.w - rb.y + 1.0f);
    unsigned long long bits = 0ULL;
    int nCols = PRE - colBase; if (nCols > 64) nCols = 64;

    for (int jj = 0; jj < nCols; ++jj) {
        int col = colBase + jj;
        if (col <= row) continue;
        float4 cb = s_col[jj];
        float xx1 = fmaxf(rb.x, cb.x);
        float yy1 = fmaxf(rb.y, cb.y);
        float xx2 = fminf(rb.z, cb.z);
        float yy2 = fminf(rb.w, cb.w);
        float iw = fmaxf(xx2 - xx1 + 1.0f, 0.0f);
        float ih = fmaxf(yy2 - yy1 + 1.0f, 0.0f);
        float inter = iw * ih;
        float cArea = (cb.z - cb.x + 1.0f) * (cb.w - cb.y + 1.0f);
        float iou = inter / (rArea + cArea - inter);
        if (iou > NMS_THR) bits |= (1ULL << jj);
    }
    g_mask[img][row][colBlk] = bits;
}

// =============================================================================
// Kernel C: greedy scan, 1 warp/image, shfl-free steady state.
// Two prefetched register streams per lane:
//   mbuf[d] = g_mask[i][lane]   (lane's owned removed-word contribution)
//   sbuf[d] = g_mask[i][i>>6]   (broadcast: in-word suppression bits)
// Per candidate: kept = !(cur & bit);  rw |= kept?m:0;  cur |= kept?ms:0.
// One shfl per 64 candidates (refresh cur from lane w's rw).
// Output layout: boxes[8*1000*4] | scores[8*1000] | valid[8*1000]  (float32)
// =============================================================================
__global__ __launch_bounds__(256)
void nms_reduce_kernel(float* __restrict__ out)
{
    const int img = blockIdx.x;
    const int tid = threadIdx.x;

    __shared__ int s_kept[POST];
    __shared__ int s_nk;

    float* outB = out;                       // (8,1000,4)
    float* outS = out + NIMG * POST * 4;     // (8,1000)
    float* outV = out + NIMG * POST * 5;     // (8,1000)

    if (tid >= 32) {
        // warps 1..7: zero the output region for this image (overlaps with scan)
        int t = tid - 32;
        for (int i = t; i < POST * 4; i += 224) outB[img * POST * 4 + i] = 0.0f;
        for (int i = t; i < POST;     i += 224) {
            outS[img * POST + i] = 0.0f;
            outV[img * POST + i] = 0.0f;
        }
    } else {
        const int lane = tid;

        // removed-word init: invalid candidates are "removed" from the start
        unsigned long long rw;
        {
            const unsigned long long* vp = (const unsigned long long*)g_valid[img];
            unsigned long long bits = 0ULL;
            #pragma unroll
            for (int q = 0; q < 8; ++q) {
                unsigned long long v8 = vp[lane * 8 + q];
                #pragma unroll
                for (int b = 0; b < 8; ++b)
                    if ((v8 >> (8 * b)) & 0xFFull) bits |= 1ULL << (q * 8 + b);
            }
            rw = ~bits;                      // lane owns removed word `lane`
        }

        unsigned long long mbuf[PFD], sbuf[PFD];
        #pragma unroll
        for (int d = 0; d < PFD; ++d) {
            mbuf[d] = g_mask[img][d][lane];
            sbuf[d] = g_mask[img][d][0];     // d < 64 -> word 0
        }

        int k = 0;
        unsigned long long cur = 0ULL;
        for (int base = 0; base < PRE; base += PFD) {
            #pragma unroll
            for (int d = 0; d < PFD; ++d) {
                const int i = base + d;
                unsigned long long m  = mbuf[d];
                unsigned long long ms = sbuf[d];
                int pf = i + PFD;
                if (pf < PRE) {
                    mbuf[d] = g_mask[img][pf][lane];
                    sbuf[d] = g_mask[img][pf][pf >> 6];
                }
                int w = i >> 6;
                if ((i & 63) == 0)
                    cur = __shfl_sync(0xFFFFFFFFu, rw, w);   // uniform, 1 per 64
                unsigned long long bit = 1ULL << (i & 63);
                bool kept = !(cur & bit);
                rw  |= kept ? m  : 0ULL;     // branchless (SEL + OR)
                cur |= kept ? ms : 0ULL;
                if (kept) {
                    if (lane == 0 && k < POST) s_kept[k] = i;
                    ++k;                      // uniform across lanes
                }
            }
        }
        if (lane == 0) s_nk = (k < POST) ? k : POST;
    }
    __syncthreads();

    const int nk = s_nk;
    for (int j = tid; j < nk; j += 256) {
        int i = s_kept[j];
        float4 b = g_boxes[img][i];
        ((float4*)outB)[img * POST + j] = b;
        outS[img * POST + j] = g_scores[img][i];
        outV[img * POST + j] = 1.0f;
    }
}

// =============================================================================
extern "C" void kernel_launch(void* const* d_in, const int* in_sizes, int n_in,
                              void* d_out, int out_size)
{
    const float* obj = (const float*)d_in[0];   // (8,3,100,100)
    const float* reg = (const float*)d_in[1];   // (8,12,100,100)
    const float* anc = (const float*)d_in[2];   // (8,30000,4)
    float* out = (float*)d_out;
    (void)in_sizes; (void)n_in; (void)out_size;

    const int smemA = 120000 + PREP * 8;        // 136384 bytes dynamic
    cudaFuncSetAttribute(topk_decode_kernel,
                         cudaFuncAttributeMaxDynamicSharedMemorySize, smemA);

    sigmoid_kernel<<<(NIMG * NANC + 255) / 256, 256>>>(obj);
    topk_decode_kernel<<<NIMG, 1024, smemA>>>(reg, anc);
    dim3 gB(NWRD, 8, NIMG);
    nms_mask_kernel<<<gB, 256>>>();
    nms_reduce_kernel<<<NIMG, 256>>>(out);
}

// round 6
// speedup vs baseline: 1.3170x; 1.3170x over previous
#include <cuda_runtime.h>
#include <cuda_bf16.h>
#include <cstdint>

#define NIMG 8
#define NA   3
#define HH   100
#define WW   100
#define NHW  10000
#define NANC 30000          // H*W*A
#define PRE  2000
#define PREP 2048           // padded to pow2 for bitonic sort
#define POST 1000
#define NWRD 32             // ceil(2000/64) mask words per row
#define IMGW 1600.0f
#define BBOX_CLIP 4.135166556742356f   // log(1000/16)
#define NMS_THR 0.7f
#define PFD  16             // prefetch depth in kernel C

// ---------------- device-global scratch (no runtime allocation) ----------------
__device__ unsigned int       g_sb[NIMG][NANC];            // sigmoid score bits, anchor order
__device__ float4             g_boxes[NIMG][PRE];
__device__ float              g_scores[NIMG][PRE];
__device__ unsigned char      g_valid[NIMG][PREP];         // padded: lanes read 64B each
__device__ unsigned long long g_mask[NIMG][PRE][NWRD];     // ~4.1 MB

// =============================================================================
// Kernel 0: full-chip sigmoid + layout transform (N,A,H,W) -> [img][hw*3+a]
// =============================================================================
__global__ __launch_bounds__(256)
void sigmoid_kernel(const float* __restrict__ obj_all)
{
    int gid = blockIdx.x * 256 + threadIdx.x;
    if (gid >= NIMG * NANC) return;
    int img = gid / NANC;
    int r   = gid - img * NANC;      // r = a*NHW + hw  (input memory order -> coalesced read)
    int a   = r / NHW;
    int hw  = r - a * NHW;
    float o = obj_all[gid];
    float s = 1.0f / (1.0f + expf(-o));
    g_sb[img][hw * NA + a] = __float_as_uint(s);   // scores in (0,1): bits monotonic
}

// =============================================================================
// Kernel A: radix-select threshold -> compact -> bitonic sort -> decode/clip.
// One block (1024 thr) per image.
// =============================================================================
__global__ __launch_bounds__(1024)
void topk_decode_kernel(const float* __restrict__ reg_all,
                        const float* __restrict__ anc_all)
{
    extern __shared__ unsigned char smem_raw[];
    unsigned int*       s_sb   = (unsigned int*)smem_raw;                  // 30000 u32
    unsigned long long* s_keys = (unsigned long long*)(smem_raw + 120000); // 2048 u64

    __shared__ unsigned int s_hist[256];
    __shared__ unsigned int s_scan[256];
    __shared__ unsigned int s_cnt;
    __shared__ unsigned int s_prefix;
    __shared__ int          s_K;

    const int img = blockIdx.x;
    const int tid = threadIdx.x;

    // ---- phase 1: coalesced vector copy of score bits into smem ----
    {
        const uint4* src = (const uint4*)g_sb[img];          // 7500 uint4
        uint4* dst = (uint4*)s_sb;
        for (int i = tid; i < NANC / 4; i += 1024) dst[i] = src[i];
    }
    if (tid == 0) { s_prefix = 0; s_K = PRE; }
    __syncthreads();

    // ---- phase 2: 4-pass MSB radix select for the PRE-th largest value ----
    unsigned int pmask = 0;
    for (int pass = 0; pass < 4; ++pass) {
        int shift = 24 - 8 * pass;
        if (tid < 256) s_hist[tid] = 0;
        __syncthreads();
        unsigned int prefix = s_prefix;
        for (int i = tid; i < NANC; i += 1024) {
            unsigned int v = s_sb[i];
            if ((v & pmask) == prefix)
                atomicAdd(&s_hist[(v >> shift) & 255u], 1u);
        }
        __syncthreads();
        // parallel inclusive suffix-sum over 256 bins
        if (tid < 256) s_scan[tid] = s_hist[tid];
        __syncthreads();
        for (int off = 1; off < 256; off <<= 1) {
            unsigned int add = 0;
            if (tid < 256) add = (tid + off < 256) ? s_scan[tid + off] : 0u;
            __syncthreads();
            if (tid < 256) s_scan[tid] += add;
            __syncthreads();
        }
        int Kc = s_K;
        __syncthreads();
        if (tid < 256) {
            unsigned int cs  = s_scan[tid];
            unsigned int nxt = (tid < 255) ? s_scan[tid + 1] : 0u;
            if ((int)cs >= Kc && (int)nxt < Kc) {
                s_K = Kc - (int)nxt;                       // remaining within this bin
                s_prefix = s_prefix | ((unsigned int)tid << shift);
            }
        }
        pmask |= (0xFFu << shift);
        __syncthreads();
    }
    const unsigned int T = s_prefix;   // exact bits of the PRE-th largest score

    // ---- phase 3: compact candidates >= T ----
    if (tid == 0) s_cnt = 0;
    __syncthreads();
    for (int i = tid; i < NANC; i += 1024) {
        unsigned int v = s_sb[i];
        if (v >= T) {
            unsigned int pos = atomicAdd(&s_cnt, 1u);
            if (pos < PREP)
                s_keys[pos] = ((unsigned long long)v << 32) |
                              (unsigned long long)(~(unsigned int)i);
        }
    }
    __syncthreads();
    unsigned int n = s_cnt; if (n > PREP) n = PREP;
    for (int i = tid; i < PREP; i += 1024)
        if (i >= (int)n) s_keys[i] = 0ULL;
    __syncthreads();

    // ---- phase 4: bitonic sort (descending) of 2048 keys ----
    for (int k = 2; k <= PREP; k <<= 1) {
        for (int j = k >> 1; j > 0; j >>= 1) {
            for (int i = tid; i < PREP; i += 1024) {
                int l = i ^ j;
                if (l > i) {
                    unsigned long long a = s_keys[i];
                    unsigned long long b = s_keys[l];
                    bool up = ((i & k) == 0);
                    if ((a < b) == up) { s_keys[i] = b; s_keys[l] = a; }
                }
            }
            __syncthreads();
        }
    }

    // ---- phase 5: decode / clip / validity for top PRE ----
    const float* reg = reg_all + (size_t)img * NA * 4 * NHW;
    const float4* anc = (const float4*)anc_all + (size_t)img * NANC;
    for (int j = tid; j < PRE; j += 1024) {
        unsigned long long key = s_keys[j];
        unsigned int idx = ~(unsigned int)(key & 0xFFFFFFFFull);
        float score = __uint_as_float((unsigned int)(key >> 32));

        int hw = idx / NA;
        int a  = idx - hw * NA;
        const float* rb = reg + (a * 4) * NHW + hw;
        float dx = rb[0];
        float dy = rb[NHW];
        float dw = rb[2 * NHW];
        float dh = rb[3 * NHW];
        dw = fminf(dw, BBOX_CLIP);
        dh = fminf(dh, BBOX_CLIP);

        float4 A4 = anc[idx];
        float w  = A4.z - A4.x + 1.0f;
        float h  = A4.w - A4.y + 1.0f;
        float cx = A4.x + 0.5f * w;
        float cy = A4.y + 0.5f * h;

        float pcx = dx * w + cx;
        float pcy = dy * h + cy;
        float pw  = expf(dw) * w;
        float ph  = expf(dh) * h;

        float x1 = pcx - 0.5f * pw;
        float y1 = pcy - 0.5f * ph;
        float x2 = pcx + 0.5f * pw - 1.0f;
        float y2 = pcy + 0.5f * ph - 1.0f;

        x1 = fminf(fmaxf(x1, 0.0f), IMGW - 1.0f);
        x2 = fminf(fmaxf(x2, 0.0f), IMGW - 1.0f);
        y1 = fminf(fmaxf(y1, 0.0f), IMGW - 1.0f);
        y2 = fminf(fmaxf(y2, 0.0f), IMGW - 1.0f);

        float ws = x2 - x1 + 1.0f;
        float hs = y2 - y1 + 1.0f;
        float xc = x1 + ws * 0.5f;
        float yc = y1 + hs * 0.5f;
        unsigned char v = (ws >= 0.0f) & (hs >= 0.0f) & (xc < IMGW) & (yc < IMGW);

        g_boxes[img][j]  = make_float4(x1, y1, x2, y2);
        g_scores[img][j] = score;
        g_valid[img][j]  = v;
    }
    // zero the pad bytes so kernel C's packed reads are well-defined
    for (int j = PRE + tid; j < PREP; j += 1024) g_valid[img][j] = 0;
}

// =============================================================================
// Kernel B: NMS suppression bitmask. grid (colBlk=32, rowQuad=8, img=8), 256 thr
// =============================================================================
__global__ __launch_bounds__(256)
void nms_mask_kernel()
{
    const int img    = blockIdx.z;
    const int colBlk = blockIdx.x;
    const int row    = blockIdx.y * 256 + threadIdx.x;

    __shared__ float4 s_col[64];
    const int colBase = colBlk * 64;
    if (threadIdx.x < 64) {
        int c = colBase + threadIdx.x;
        if (c < PRE) s_col[threadIdx.x] = g_boxes[img][c];
    }
    __syncthreads();

    if (row >= PRE) return;
    if (colBlk < (row >> 6)) {             // tile entirely below diagonal
        g_mask[img][row][colBlk] = 0ULL;
        return;
    }

    float4 rb = g_boxes[img][row];
    float rArea = (rb.z - rb.x + 1.0f) * (rb.w - rb.y + 1.0f);
    unsigned long long bits = 0ULL;
    int nCols = PRE - colBase; if (nCols > 64) nCols = 64;

    for (int jj = 0; jj < nCols; ++jj) {
        int col = colBase + jj;
        if (col <= row) continue;
        float4 cb = s_col[jj];
        float xx1 = fmaxf(rb.x, cb.x);
        float yy1 = fmaxf(rb.y, cb.y);
        float xx2 = fminf(rb.z, cb.z);
        float yy2 = fminf(rb.w, cb.w);
        float iw = fmaxf(xx2 - xx1 + 1.0f, 0.0f);
        float ih = fmaxf(yy2 - yy1 + 1.0f, 0.0f);
        float inter = iw * ih;
        float cArea = (cb.z - cb.x + 1.0f) * (cb.w - cb.y + 1.0f);
        float iou = inter / (rArea + cArea - inter);
        if (iou > NMS_THR) bits |= (1ULL << jj);
    }
    g_mask[img][row][colBlk] = bits;
}

// =============================================================================
// Kernel C: greedy scan, 1 warp/image. Single prefetched load stream (PFD deep).
// Lane L owns removed-word L (rw). Per candidate i (word w = i>>6):
//   m  = mask row i, word L        (prefetched register stream)
//   ms = mask row i, word w        = __shfl(m, w)   -- OFF the serial chain
//   kept = !(cur & bit);  rw |= kept?m:0;  cur |= kept?ms:0
// cur is refreshed from lane w's rw once per 64 candidates. Early exit at POST.
// Output layout: boxes[8*1000*4] | scores[8*1000] | valid[8*1000]  (float32)
// =============================================================================
__global__ __launch_bounds__(256)
void nms_reduce_kernel(float* __restrict__ out)
{
    const int img = blockIdx.x;
    const int tid = threadIdx.x;

    __shared__ int s_kept[POST];
    __shared__ int s_nk;

    float* outB = out;                       // (8,1000,4)
    float* outS = out + NIMG * POST * 4;     // (8,1000)
    float* outV = out + NIMG * POST * 5;     // (8,1000)

    if (tid >= 32) {
        // warps 1..7: zero the output region for this image (overlaps with scan)
        int t = tid - 32;
        for (int i = t; i < POST * 4; i += 224) outB[img * POST * 4 + i] = 0.0f;
        for (int i = t; i < POST;     i += 224) {
            outS[img * POST + i] = 0.0f;
            outV[img * POST + i] = 0.0f;
        }
    } else {
        const int lane = tid;

        // removed-word init: invalid candidates are "removed" from the start
        unsigned long long rw;
        {
            const unsigned long long* vp = (const unsigned long long*)g_valid[img];
            unsigned long long bits = 0ULL;
            #pragma unroll
            for (int q = 0; q < 8; ++q) {
                unsigned long long v8 = vp[lane * 8 + q];
                #pragma unroll
                for (int b = 0; b < 8; ++b)
                    if ((v8 >> (8 * b)) & 0xFFull) bits |= 1ULL << (q * 8 + b);
            }
            rw = ~bits;                      // lane owns removed word `lane`
        }

        unsigned long long buf[PFD];
        #pragma unroll
        for (int d = 0; d < PFD; ++d) buf[d] = g_mask[img][d][lane];

        int k = 0;
        unsigned long long cur = 0ULL;
        for (int base = 0; base < PRE; base += PFD) {
            #pragma unroll
            for (int d = 0; d < PFD; ++d) {
                const int i = base + d;
                unsigned long long m = buf[d];
                int pf = i + PFD;
                if (pf < PRE) buf[d] = g_mask[img][pf][lane];   // deep prefetch
                const int w = i >> 6;
                // row i's own-word suppression bits live in lane w's m:
                unsigned long long ms = __shfl_sync(0xFFFFFFFFu, m, w);
                if ((i & 63) == 0)
                    cur = __shfl_sync(0xFFFFFFFFu, rw, w);      // 1 per 64 cands
                unsigned long long bit = 1ULL << (i & 63);
                bool kept = !(cur & bit);
                rw  |= kept ? m  : 0ULL;     // branchless
                cur |= kept ? ms : 0ULL;
                if (kept) {
                    if (lane == 0) s_kept[k] = i;
                    if (++k >= POST) goto scan_done;   // warp-uniform
                }
            }
        }
    scan_done:
        if (lane == 0) s_nk = k;
    }
    __syncthreads();

    const int nk = s_nk;
    for (int j = tid; j < nk; j += 256) {
        int i = s_kept[j];
        float4 b = g_boxes[img][i];
        ((float4*)outB)[img * POST + j] = b;
        outS[img * POST + j] = g_scores[img][i];
        outV[img * POST + j] = 1.0f;
    }
}

// =============================================================================
extern "C" void kernel_launch(void* const* d_in, const int* in_sizes, int n_in,
                              void* d_out, int out_size)
{
    const float* obj = (const float*)d_in[0];   // (8,3,100,100)
    const float* reg = (const float*)d_in[1];   // (8,12,100,100)
    const float* anc = (const float*)d_in[2];   // (8,30000,4)
    float* out = (float*)d_out;
    (void)in_sizes; (void)n_in; (void)out_size;

    const int smemA = 120000 + PREP * 8;        // 136384 bytes dynamic
    cudaFuncSetAttribute(topk_decode_kernel,
                         cudaFuncAttributeMaxDynamicSharedMemorySize, smemA);

    sigmoid_kernel<<<(NIMG * NANC + 255) / 256, 256>>>(obj);
    topk_decode_kernel<<<NIMG, 1024, smemA>>>(reg, anc);
    dim3 gB(NWRD, 8, NIMG);
    nms_mask_kernel<<<gB, 256>>>();
    nms_reduce_kernel<<<NIMG, 256>>>(out);
}

// round 7
// speedup vs baseline: 1.6886x; 1.2821x over previous
#include <cuda_runtime.h>
#include <cuda_bf16.h>
#include <cstdint>

#define NIMG 8
#define NA   3
#define HH   100
#define WW   100
#define NHW  10000
#define NANC 30000          // H*W*A
#define PRE  2000
#define PREP 2048           // padded to pow2 for bitonic sort
#define POST 1000
#define NWRD 32             // ceil(2000/64) mask words per row
#define IMGW 1600.0f
#define BBOX_CLIP 4.135166556742356f   // log(1000/16)
#define NMS_THR 0.7f
#define SC   8              // kernel-C sub-chunk (candidates per batch)
#define NSC  (PRE / SC)     // 250

typedef unsigned long long u64;

// ---------------- device-global scratch (no runtime allocation) ----------------
__device__ unsigned int       g_sb[NIMG][NANC];            // sigmoid score bits, anchor order
__device__ float4             g_boxes[NIMG][PRE];
__device__ float              g_scores[NIMG][PRE];
__device__ unsigned char      g_valid[NIMG][PREP];         // padded: lanes read 64B each
__device__ u64                g_mask[NIMG][PRE][NWRD];     // ~4.1 MB

// =============================================================================
// Kernel 0: full-chip sigmoid + layout transform (N,A,H,W) -> [img][hw*3+a]
// =============================================================================
__global__ __launch_bounds__(256)
void sigmoid_kernel(const float* __restrict__ obj_all)
{
    int gid = blockIdx.x * 256 + threadIdx.x;
    if (gid >= NIMG * NANC) return;
    int img = gid / NANC;
    int r   = gid - img * NANC;      // r = a*NHW + hw  (input memory order -> coalesced read)
    int a   = r / NHW;
    int hw  = r - a * NHW;
    float o = obj_all[gid];
    float s = 1.0f / (1.0f + expf(-o));
    g_sb[img][hw * NA + a] = __float_as_uint(s);   // scores in (0,1): bits monotonic
}

// =============================================================================
// Kernel A: radix-select threshold -> compact -> bitonic sort -> decode/clip.
// One block (1024 thr) per image.
// =============================================================================
__global__ __launch_bounds__(1024)
void topk_decode_kernel(const float* __restrict__ reg_all,
                        const float* __restrict__ anc_all)
{
    extern __shared__ unsigned char smem_raw[];
    unsigned int* s_sb   = (unsigned int*)smem_raw;                  // 30000 u32
    u64*          s_keys = (u64*)(smem_raw + 120000);                // 2048 u64

    __shared__ unsigned int s_hist[256];
    __shared__ unsigned int s_scan[256];
    __shared__ unsigned int s_cnt;
    __shared__ unsigned int s_prefix;
    __shared__ int          s_K;

    const int img = blockIdx.x;
    const int tid = threadIdx.x;

    // ---- phase 1: coalesced vector copy of score bits into smem ----
    {
        const uint4* src = (const uint4*)g_sb[img];          // 7500 uint4
        uint4* dst = (uint4*)s_sb;
        for (int i = tid; i < NANC / 4; i += 1024) dst[i] = src[i];
    }
    if (tid == 0) { s_prefix = 0; s_K = PRE; }
    __syncthreads();

    // ---- phase 2: 4-pass MSB radix select for the PRE-th largest value ----
    unsigned int pmask = 0;
    for (int pass = 0; pass < 4; ++pass) {
        int shift = 24 - 8 * pass;
        if (tid < 256) s_hist[tid] = 0;
        __syncthreads();
        unsigned int prefix = s_prefix;
        for (int i = tid; i < NANC; i += 1024) {
            unsigned int v = s_sb[i];
            if ((v & pmask) == prefix)
                atomicAdd(&s_hist[(v >> shift) & 255u], 1u);
        }
        __syncthreads();
        // parallel inclusive suffix-sum over 256 bins
        if (tid < 256) s_scan[tid] = s_hist[tid];
        __syncthreads();
        for (int off = 1; off < 256; off <<= 1) {
            unsigned int add = 0;
            if (tid < 256) add = (tid + off < 256) ? s_scan[tid + off] : 0u;
            __syncthreads();
            if (tid < 256) s_scan[tid] += add;
            __syncthreads();
        }
        int Kc = s_K;
        __syncthreads();
        if (tid < 256) {
            unsigned int cs  = s_scan[tid];
            unsigned int nxt = (tid < 255) ? s_scan[tid + 1] : 0u;
            if ((int)cs >= Kc && (int)nxt < Kc) {
                s_K = Kc - (int)nxt;                       // remaining within this bin
                s_prefix = s_prefix | ((unsigned int)tid << shift);
            }
        }
        pmask |= (0xFFu << shift);
        __syncthreads();
    }
    const unsigned int T = s_prefix;   // exact bits of the PRE-th largest score

    // ---- phase 3: compact candidates >= T ----
    if (tid == 0) s_cnt = 0;
    __syncthreads();
    for (int i = tid; i < NANC; i += 1024) {
        unsigned int v = s_sb[i];
        if (v >= T) {
            unsigned int pos = atomicAdd(&s_cnt, 1u);
            if (pos < PREP)
                s_keys[pos] = ((u64)v << 32) | (u64)(~(unsigned int)i);
        }
    }
    __syncthreads();
    unsigned int n = s_cnt; if (n > PREP) n = PREP;
    for (int i = tid; i < PREP; i += 1024)
        if (i >= (int)n) s_keys[i] = 0ULL;
    __syncthreads();

    // ---- phase 4: bitonic sort (descending) of 2048 keys ----
    for (int k = 2; k <= PREP; k <<= 1) {
        for (int j = k >> 1; j > 0; j >>= 1) {
            for (int i = tid; i < PREP; i += 1024) {
                int l = i ^ j;
                if (l > i) {
                    u64 a = s_keys[i];
                    u64 b = s_keys[l];
                    bool up = ((i & k) == 0);
                    if ((a < b) == up) { s_keys[i] = b; s_keys[l] = a; }
                }
            }
            __syncthreads();
        }
    }

    // ---- phase 5: decode / clip / validity for top PRE ----
    const float* reg = reg_all + (size_t)img * NA * 4 * NHW;
    const float4* anc = (const float4*)anc_all + (size_t)img * NANC;
    for (int j = tid; j < PRE; j += 1024) {
        u64 key = s_keys[j];
        unsigned int idx = ~(unsigned int)(key & 0xFFFFFFFFull);
        float score = __uint_as_float((unsigned int)(key >> 32));

        int hw = idx / NA;
        int a  = idx - hw * NA;
        const float* rb = reg + (a * 4) * NHW + hw;
        float dx = rb[0];
        float dy = rb[NHW];
        float dw = rb[2 * NHW];
        float dh = rb[3 * NHW];
        dw = fminf(dw, BBOX_CLIP);
        dh = fminf(dh, BBOX_CLIP);

        float4 A4 = anc[idx];
        float w  = A4.z - A4.x + 1.0f;
        float h  = A4.w - A4.y + 1.0f;
        float cx = A4.x + 0.5f * w;
        float cy = A4.y + 0.5f * h;

        float pcx = dx * w + cx;
        float pcy = dy * h + cy;
        float pw  = expf(dw) * w;
        float ph  = expf(dh) * h;

        float x1 = pcx - 0.5f * pw;
        float y1 = pcy - 0.5f * ph;
        float x2 = pcx + 0.5f * pw - 1.0f;
        float y2 = pcy + 0.5f * ph - 1.0f;

        x1 = fminf(fmaxf(x1, 0.0f), IMGW - 1.0f);
        x2 = fminf(fmaxf(x2, 0.0f), IMGW - 1.0f);
        y1 = fminf(fmaxf(y1, 0.0f), IMGW - 1.0f);
        y2 = fminf(fmaxf(y2, 0.0f), IMGW - 1.0f);

        float ws = x2 - x1 + 1.0f;
        float hs = y2 - y1 + 1.0f;
        float xc = x1 + ws * 0.5f;
        float yc = y1 + hs * 0.5f;
        unsigned char v = (ws >= 0.0f) & (hs >= 0.0f) & (xc < IMGW) & (yc < IMGW);

        g_boxes[img][j]  = make_float4(x1, y1, x2, y2);
        g_scores[img][j] = score;
        g_valid[img][j]  = v;
    }
    // zero the pad bytes so kernel C's packed reads are well-defined
    for (int j = PRE + tid; j < PREP; j += 1024) g_valid[img][j] = 0;
}

// =============================================================================
// Kernel B: NMS suppression bitmask. grid (colBlk=32, rowQuad=8, img=8), 256 thr
// =============================================================================
__global__ __launch_bounds__(256)
void nms_mask_kernel()
{
    const int img    = blockIdx.z;
    const int colBlk = blockIdx.x;
    const int row    = blockIdx.y * 256 + threadIdx.x;

    __shared__ float4 s_col[64];
    const int colBase = colBlk * 64;
    if (threadIdx.x < 64) {
        int c = colBase + threadIdx.x;
        if (c < PRE) s_col[threadIdx.x] = g_boxes[img][c];
    }
    __syncthreads();

    if (row >= PRE) return;
    if (colBlk < (row >> 6)) {             // tile entirely below diagonal
        g_mask[img][row][colBlk] = 0ULL;
        return;
    }

    float4 rb = g_boxes[img][row];
    float rArea = (rb.z - rb.x + 1.0f) * (rb.w - rb.y + 1.0f);
    u64 bits = 0ULL;
    int nCols = PRE - colBase; if (nCols > 64) nCols = 64;

    for (int jj = 0; jj < nCols; ++jj) {
        int col = colBase + jj;
        if (col <= row) continue;
        float4 cb = s_col[jj];
        float xx1 = fmaxf(rb.x, cb.x);
        float yy1 = fmaxf(rb.y, cb.y);
        float xx2 = fminf(rb.z, cb.z);
        float yy2 = fminf(rb.w, cb.w);
        float iw = fmaxf(xx2 - xx1 + 1.0f, 0.0f);
        float ih = fmaxf(yy2 - yy1 + 1.0f, 0.0f);
        float inter = iw * ih;
        float cArea = (cb.z - cb.x + 1.0f) * (cb.w - cb.y + 1.0f);
        float iou = inter / (rArea + cArea - inter);
        if (iou > NMS_THR) bits |= (1ULL << jj);
    }
    g_mask[img][row][colBlk] = bits;
}

// =============================================================================
// Kernel C: greedy scan, 1 warp/image.  Sub-chunked structure so ptxas can
// batch loads:
//   per 8-candidate sub-chunk:
//     (1) 8 back-to-back LDGs into a depth-4 circular register buffer (24-cand
//         lead -> ~2 sub-chunk computes ~500cyc > L2 lat, MLP ~24)
//     (2) 8 batched shfls -> broadcast words ms[] (word idx constant in chunk)
//     (3) pure-ALU serial decision chain; keep-record = one predicated STS
//     (4) cur refresh 1 shfl / 64 cands; uniform early-exit per sub-chunk
// Output layout: boxes[8*1000*4] | scores[8*1000] | valid[8*1000]  (float32)
// =============================================================================
__global__ __launch_bounds__(256)
void nms_reduce_kernel(float* __restrict__ out)
{
    const int img = blockIdx.x;
    const int tid = threadIdx.x;

    __shared__ int s_kept[POST];
    __shared__ int s_nk;

    float* outB = out;                       // (8,1000,4)
    float* outS = out + NIMG * POST * 4;     // (8,1000)
    float* outV = out + NIMG * POST * 5;     // (8,1000)

    if (tid >= 32) {
        // warps 1..7: zero the output region for this image (overlaps with scan)
        int t = tid - 32;
        for (int i = t; i < POST * 4; i += 224) outB[img * POST * 4 + i] = 0.0f;
        for (int i = t; i < POST;     i += 224) {
            outS[img * POST + i] = 0.0f;
            outV[img * POST + i] = 0.0f;
        }
    } else {
        const int lane = tid;

        // removed-word init: invalid candidates are "removed" from the start
        u64 rw;
        {
            const u64* vp = (const u64*)g_valid[img];
            u64 bits = 0ULL;
            #pragma unroll
            for (int q = 0; q < 8; ++q) {
                u64 v8 = vp[lane * 8 + q];
                #pragma unroll
                for (int b = 0; b < 8; ++b)
                    if ((v8 >> (8 * b)) & 0xFFull) bits |= 1ULL << (q * 8 + b);
            }
            rw = ~bits;                      // lane owns removed word `lane`
        }

        u64 buf[4][SC];                      // depth-4 circular buffer
        #pragma unroll
        for (int s = 0; s < 3; ++s)
            #pragma unroll
            for (int j = 0; j < SC; ++j)
                buf[s][j] = g_mask[img][s * SC + j][lane];

        int k = 0;
        u64 cur = 0ULL;
        for (int sc = 0; sc < NSC; ++sc) {
            const int b = sc * SC;
            const int slot = sc & 3;

            // (1) straight-line load batch for sub-chunk sc+3
            {
                const int nb = b + 3 * SC;
                if (nb < PRE) {
                    const int ns = (sc + 3) & 3;
                    #pragma unroll
                    for (int j = 0; j < SC; ++j)
                        buf[ns][j] = g_mask[img][nb + j][lane];
                }
            }

            const int w = b >> 6;            // word idx, constant in sub-chunk
            if ((b & 63) == 0)
                cur = __shfl_sync(0xFFFFFFFFu, rw, w);     // 1 per 64 cands

            // (2) batched broadcast-word shfls (off the serial chain)
            u64 ms[SC];
            #pragma unroll
            for (int j = 0; j < SC; ++j)
                ms[j] = __shfl_sync(0xFFFFFFFFu, buf[slot][j], w);

            // (3) pure-ALU serial chain, predicated recording
            const u64 bb = 1ULL << (b & 63);
            #pragma unroll
            for (int j = 0; j < SC; ++j) {
                const u64 bitj = bb << j;
                const bool kept = (cur & bitj) == 0ULL;
                cur |= kept ? ms[j] : 0ULL;
                rw  |= kept ? buf[slot][j] : 0ULL;
                if (kept & (lane == 0) & (k < POST)) s_kept[k] = b + j;
                k += (int)kept;              // uniform across lanes
            }

            // (4) uniform early exit
            if (k >= POST) break;
        }
        if (lane == 0) s_nk = (k < POST) ? k : POST;
    }
    __syncthreads();

    const int nk = s_nk;
    for (int j = tid; j < nk; j += 256) {
        int i = s_kept[j];
        float4 b = g_boxes[img][i];
        ((float4*)outB)[img * POST + j] = b;
        outS[img * POST + j] = g_scores[img][i];
        outV[img * POST + j] = 1.0f;
    }
}

// =============================================================================
extern "C" void kernel_launch(void* const* d_in, const int* in_sizes, int n_in,
                              void* d_out, int out_size)
{
    const float* obj = (const float*)d_in[0];   // (8,3,100,100)
    const float* reg = (const float*)d_in[1];   // (8,12,100,100)
    const float* anc = (const float*)d_in[2];   // (8,30000,4)
    float* out = (float*)d_out;
    (void)in_sizes; (void)n_in; (void)out_size;

    const int smemA = 120000 + PREP * 8;        // 136384 bytes dynamic
    cudaFuncSetAttribute(topk_decode_kernel,
                         cudaFuncAttributeMaxDynamicSharedMemorySize, smemA);

    sigmoid_kernel<<<(NIMG * NANC + 255) / 256, 256>>>(obj);
    topk_decode_kernel<<<NIMG, 1024, smemA>>>(reg, anc);
    dim3 gB(NWRD, 8, NIMG);
    nms_mask_kernel<<<gB, 256>>>();
    nms_reduce_kernel<<<NIMG, 256>>>(out);
}

// round 9
// speedup vs baseline: 1.7887x; 1.0593x over previous
#include <cuda_runtime.h>
#include <cuda_bf16.h>
#include <cstdint>

#define NIMG 8
#define NA   3
#define HH   100
#define WW   100
#define NHW  10000
#define NANC 30000          // H*W*A
#define PRE  2000
#define PREP 2048           // padded to pow2 for bitonic sort
#define POST 1000
#define NWRD 32             // ceil(2000/64) mask words per row
#define IMGW 1600.0f
#define BBOX_CLIP 4.135166556742356f   // log(1000/16)
#define NMS_THR 0.7f
#define SC   8              // kernel-C sub-chunk (candidates per batch)
#define NSC  (PRE / SC)     // 250

typedef unsigned long long u64;

// ---------------- device-global scratch (no runtime allocation) ----------------
__device__ unsigned int       g_sb[NIMG][NANC];            // sigmoid score bits, anchor order
__device__ float4             g_boxes[NIMG][PRE];
__device__ float              g_scores[NIMG][PRE];
__device__ unsigned char      g_valid[NIMG][PREP];         // padded: lanes read 64B each
__device__ u64                g_mask[NIMG][PRE][NWRD];     // ~4.1 MB

// =============================================================================
// Kernel 0: full-chip sigmoid + layout transform (N,A,H,W) -> [img][hw*3+a]
// =============================================================================
__global__ __launch_bounds__(256)
void sigmoid_kernel(const float* __restrict__ obj_all)
{
    int gid = blockIdx.x * 256 + threadIdx.x;
    if (gid >= NIMG * NANC) return;
    int img = gid / NANC;
    int r   = gid - img * NANC;      // r = a*NHW + hw  (input memory order -> coalesced read)
    int a   = r / NHW;
    int hw  = r - a * NHW;
    float o = obj_all[gid];
    float s = 1.0f / (1.0f + expf(-o));
    g_sb[img][hw * NA + a] = __float_as_uint(s);   // scores in (0,1): bits monotonic
}

// =============================================================================
// Kernel A: radix-select threshold -> compact -> bitonic sort -> decode/clip.
// One block (1024 thr) per image.
// =============================================================================
__global__ __launch_bounds__(1024)
void topk_decode_kernel(const float* __restrict__ reg_all,
                        const float* __restrict__ anc_all)
{
    extern __shared__ unsigned char smem_raw[];
    unsigned int* s_sb   = (unsigned int*)smem_raw;                  // 30000 u32
    u64*          s_keys = (u64*)(smem_raw + 120000);                // 2048 u64

    __shared__ unsigned int s_hist[256];
    __shared__ unsigned int s_scan[256];
    __shared__ unsigned int s_cnt;
    __shared__ unsigned int s_prefix;
    __shared__ int          s_K;

    const int img = blockIdx.x;
    const int tid = threadIdx.x;

    // ---- phase 1: coalesced vector copy of score bits into smem ----
    {
        const uint4* src = (const uint4*)g_sb[img];          // 7500 uint4
        uint4* dst = (uint4*)s_sb;
        for (int i = tid; i < NANC / 4; i += 1024) dst[i] = src[i];
    }
    if (tid == 0) { s_prefix = 0; s_K = PRE; }
    __syncthreads();

    // ---- phase 2: 4-pass MSB radix select for the PRE-th largest value ----
    unsigned int pmask = 0;
    for (int pass = 0; pass < 4; ++pass) {
        int shift = 24 - 8 * pass;
        if (tid < 256) s_hist[tid] = 0;
        __syncthreads();
        unsigned int prefix = s_prefix;
        for (int i = tid; i < NANC; i += 1024) {
            unsigned int v = s_sb[i];
            if ((v & pmask) == prefix)
                atomicAdd(&s_hist[(v >> shift) & 255u], 1u);
        }
        __syncthreads();
        // parallel inclusive suffix-sum over 256 bins
        if (tid < 256) s_scan[tid] = s_hist[tid];
        __syncthreads();
        for (int off = 1; off < 256; off <<= 1) {
            unsigned int add = 0;
            if (tid < 256) add = (tid + off < 256) ? s_scan[tid + off] : 0u;
            __syncthreads();
            if (tid < 256) s_scan[tid] += add;
            __syncthreads();
        }
        int Kc = s_K;
        __syncthreads();
        if (tid < 256) {
            unsigned int cs  = s_scan[tid];
            unsigned int nxt = (tid < 255) ? s_scan[tid + 1] : 0u;
            if ((int)cs >= Kc && (int)nxt < Kc) {
                s_K = Kc - (int)nxt;                       // remaining within this bin
                s_prefix = s_prefix | ((unsigned int)tid << shift);
            }
        }
        pmask |= (0xFFu << shift);
        __syncthreads();
    }
    const unsigned int T = s_prefix;   // exact bits of the PRE-th largest score

    // ---- phase 3: compact candidates >= T ----
    if (tid == 0) s_cnt = 0;
    __syncthreads();
    for (int i = tid; i < NANC; i += 1024) {
        unsigned int v = s_sb[i];
        if (v >= T) {
            unsigned int pos = atomicAdd(&s_cnt, 1u);
            if (pos < PREP)
                s_keys[pos] = ((u64)v << 32) | (u64)(~(unsigned int)i);
        }
    }
    __syncthreads();
    unsigned int n = s_cnt; if (n > PREP) n = PREP;
    for (int i = tid; i < PREP; i += 1024)
        if (i >= (int)n) s_keys[i] = 0ULL;
    __syncthreads();

    // ---- phase 4: bitonic sort (descending) of 2048 keys ----
    for (int k = 2; k <= PREP; k <<= 1) {
        for (int j = k >> 1; j > 0; j >>= 1) {
            for (int i = tid; i < PREP; i += 1024) {
                int l = i ^ j;
                if (l > i) {
                    u64 a = s_keys[i];
                    u64 b = s_keys[l];
                    bool up = ((i & k) == 0);
                    if ((a < b) == up) { s_keys[i] = b; s_keys[l] = a; }
                }
            }
            __syncthreads();
        }
    }

    // ---- phase 5: decode / clip / validity for top PRE ----
    const float* reg = reg_all + (size_t)img * NA * 4 * NHW;
    const float4* anc = (const float4*)anc_all + (size_t)img * NANC;
    for (int j = tid; j < PRE; j += 1024) {
        u64 key = s_keys[j];
        unsigned int idx = ~(unsigned int)(key & 0xFFFFFFFFull);
        float score = __uint_as_float((unsigned int)(key >> 32));

        int hw = idx / NA;
        int a  = idx - hw * NA;
        const float* rb = reg + (a * 4) * NHW + hw;
        float dx = rb[0];
        float dy = rb[NHW];
        float dw = rb[2 * NHW];
        float dh = rb[3 * NHW];
        dw = fminf(dw, BBOX_CLIP);
        dh = fminf(dh, BBOX_CLIP);

        float4 A4 = anc[idx];
        float w  = A4.z - A4.x + 1.0f;
        float h  = A4.w - A4.y + 1.0f;
        float cx = A4.x + 0.5f * w;
        float cy = A4.y + 0.5f * h;

        float pcx = dx * w + cx;
        float pcy = dy * h + cy;
        float pw  = expf(dw) * w;
        float ph  = expf(dh) * h;

        float x1 = pcx - 0.5f * pw;
        float y1 = pcy - 0.5f * ph;
        float x2 = pcx + 0.5f * pw - 1.0f;
        float y2 = pcy + 0.5f * ph - 1.0f;

        x1 = fminf(fmaxf(x1, 0.0f), IMGW - 1.0f);
        x2 = fminf(fmaxf(x2, 0.0f), IMGW - 1.0f);
        y1 = fminf(fmaxf(y1, 0.0f), IMGW - 1.0f);
        y2 = fminf(fmaxf(y2, 0.0f), IMGW - 1.0f);

        float ws = x2 - x1 + 1.0f;
        float hs = y2 - y1 + 1.0f;
        float xc = x1 + ws * 0.5f;
        float yc = y1 + hs * 0.5f;
        unsigned char v = (ws >= 0.0f) & (hs >= 0.0f) & (xc < IMGW) & (yc < IMGW);

        g_boxes[img][j]  = make_float4(x1, y1, x2, y2);
        g_scores[img][j] = score;
        g_valid[img][j]  = v;
    }
    // zero the pad bytes so kernel C's packed reads are well-defined
    for (int j = PRE + tid; j < PREP; j += 1024) g_valid[img][j] = 0;
}

// =============================================================================
// Kernel B: NMS suppression bitmask. grid (colBlk=32, rowQuad=8, img=8), 256 thr
// =============================================================================
__global__ __launch_bounds__(256)
void nms_mask_kernel()
{
    const int img    = blockIdx.z;
    const int colBlk = blockIdx.x;
    const int row    = blockIdx.y * 256 + threadIdx.x;

    __shared__ float4 s_col[64];
    const int colBase = colBlk * 64;
    if (threadIdx.x < 64) {
        int c = colBase + threadIdx.x;
        if (c < PRE) s_col[threadIdx.x] = g_boxes[img][c];
    }
    __syncthreads();

    if (row >= PRE) return;
    if (colBlk < (row >> 6)) {             // tile entirely below diagonal
        g_mask[img][row][colBlk] = 0ULL;
        return;
    }

    float4 rb = g_boxes[img][row];
    float rArea = (rb.z - rb.x + 1.0f) * (rb.w - rb.y + 1.0f);
    u64 bits = 0ULL;
    int nCols = PRE - colBase; if (nCols > 64) nCols = 64;

    for (int jj = 0; jj < nCols; ++jj) {
        int col = colBase + jj;
        if (col <= row) continue;
        float4 cb = s_col[jj];
        float xx1 = fmaxf(rb.x, cb.x);
        float yy1 = fmaxf(rb.y, cb.y);
        float xx2 = fminf(rb.z, cb.z);
        float yy2 = fminf(rb.w, cb.w);
        float iw = fmaxf(xx2 - xx1 + 1.0f, 0.0f);
        float ih = fmaxf(yy2 - yy1 + 1.0f, 0.0f);
        float inter = iw * ih;
        float cArea = (cb.z - cb.x + 1.0f) * (cb.w - cb.y + 1.0f);
        float iou = inter / (rArea + cArea - inter);
        if (iou > NMS_THR) bits |= (1ULL << jj);
    }
    g_mask[img][row][colBlk] = bits;
}

// =============================================================================
// Kernel C: greedy scan, 1 warp/image. Fully branchless inner loop:
//   - depth-4 circular register buffer of mask words (MLP ~24)
//   - batched shfls for broadcast words (off the serial chain)
//   - per candidate: AND -> SETP -> SEL -> OR  (no divergent branch)
//   - keep record: single unconditional STS per candidate; index selects the
//     real slot k when (kept && k<POST), else a trash slot (POST). All lanes
//     store the same addr+value, so no divergence and no RMW.
//   - uniform early-exit check once per sub-chunk only
// Output layout: boxes[8*1000*4] | scores[8*1000] | valid[8*1000]  (float32)
// =============================================================================
__global__ __launch_bounds__(256)
void nms_reduce_kernel(float* __restrict__ out)
{
    const int img = blockIdx.x;
    const int tid = threadIdx.x;

    __shared__ int s_kept[POST + 1];         // slot POST = trash (never read)
    __shared__ int s_nk;

    float* outB = out;                       // (8,1000,4)
    float* outS = out + NIMG * POST * 4;     // (8,1000)
    float* outV = out + NIMG * POST * 5;     // (8,1000)

    if (tid >= 32) {
        // warps 1..7: zero the output region for this image (overlaps with scan)
        int t = tid - 32;
        for (int i = t; i < POST * 4; i += 224) outB[img * POST * 4 + i] = 0.0f;
        for (int i = t; i < POST;     i += 224) {
            outS[img * POST + i] = 0.0f;
            outV[img * POST + i] = 0.0f;
        }
    } else {
        const int lane = tid;

        // removed-word init: invalid candidates are "removed" from the start
        u64 rw;
        {
            const u64* vp = (const u64*)g_valid[img];
            u64 bits = 0ULL;
            #pragma unroll
            for (int q = 0; q < 8; ++q) {
                u64 v8 = vp[lane * 8 + q];
                #pragma unroll
                for (int b = 0; b < 8; ++b)
                    if ((v8 >> (8 * b)) & 0xFFull) bits |= 1ULL << (q * 8 + b);
            }
            rw = ~bits;                      // lane owns removed word `lane`
        }

        u64 buf[4][SC];                      // depth-4 circular buffer
        #pragma unroll
        for (int s = 0; s < 3; ++s)
            #pragma unroll
            for (int j = 0; j < SC; ++j)
                buf[s][j] = g_mask[img][s * SC + j][lane];

        int k = 0;
        u64 cur = 0ULL;
        for (int sc = 0; sc < NSC; ++sc) {
            const int b = sc * SC;
            const int slot = sc & 3;

            // (1) straight-line load batch for sub-chunk sc+3
            {
                const int nb = b + 3 * SC;
                if (nb < PRE) {
                    const int ns = (sc + 3) & 3;
                    #pragma unroll
                    for (int j = 0; j < SC; ++j)
                        buf[ns][j] = g_mask[img][nb + j][lane];
                }
            }

            const int w = b >> 6;            // word idx, constant in sub-chunk
            if ((b & 63) == 0)
                cur = __shfl_sync(0xFFFFFFFFu, rw, w);     // 1 per 64 cands

            // (2) batched broadcast-word shfls (off the serial chain)
            u64 ms[SC];
            #pragma unroll
            for (int j = 0; j < SC; ++j)
                ms[j] = __shfl_sync(0xFFFFFFFFu, buf[slot][j], w);

            // (3) pure-ALU serial chain; recording = one unconditional STS
            const u64 bb = 1ULL << (b & 63);
            #pragma unroll
            for (int j = 0; j < SC; ++j) {
                const u64 bitj = bb << j;
                const bool kept = (cur & bitj) == 0ULL;
                cur |= kept ? ms[j] : 0ULL;
                rw  |= kept ? buf[slot][j] : 0ULL;
                const int kk = (kept && k < POST) ? k : POST;  // trash slot o.w.
                s_kept[kk] = b + j;          // uniform addr+value across lanes
                k += (int)kept;              // uniform across lanes
            }

            // (4) uniform early exit
            if (k >= POST) break;
        }
        if (lane == 0) s_nk = (k < POST) ? k : POST;
    }
    __syncthreads();

    const int nk = s_nk;
    for (int j = tid; j < nk; j += 256) {
        int i = s_kept[j];
        float4 b = g_boxes[img][i];
        ((float4*)outB)[img * POST + j] = b;
        outS[img * POST + j] = g_scores[img][i];
        outV[img * POST + j] = 1.0f;
    }
}

// =============================================================================
extern "C" void kernel_launch(void* const* d_in, const int* in_sizes, int n_in,
                              void* d_out, int out_size)
{
    const float* obj = (const float*)d_in[0];   // (8,3,100,100)
    const float* reg = (const float*)d_in[1];   // (8,12,100,100)
    const float* anc = (const float*)d_in[2];   // (8,30000,4)
    float* out = (float*)d_out;
    (void)in_sizes; (void)n_in; (void)out_size;

    const int smemA = 120000 + PREP * 8;        // 136384 bytes dynamic
    cudaFuncSetAttribute(topk_decode_kernel,
                         cudaFuncAttributeMaxDynamicSharedMemorySize, smemA);

    sigmoid_kernel<<<(NIMG * NANC + 255) / 256, 256>>>(obj);
    topk_decode_kernel<<<NIMG, 1024, smemA>>>(reg, anc);
    dim3 gB(NWRD, 8, NIMG);
    nms_mask_kernel<<<gB, 256>>>();
    nms_reduce_kernel<<<NIMG, 256>>>(out);
}

// round 10
// speedup vs baseline: 2.1083x; 1.1787x over previous
#include <cuda_runtime.h>
#include <cuda_bf16.h>
#include <cstdint>

#define NIMG 8
#define NA   3
#define HH   100
#define WW   100
#define NHW  10000
#define NANC 30000          // H*W*A
#define PRE  2000
#define PREP 2048           // padded to pow2 for bitonic sort
#define POST 1000
#define NWRD 32             // ceil(2000/64) mask words per row
#define NTILE 32            // 64-row tiles
#define IMGW 1600.0f
#define BBOX_CLIP 4.135166556742356f   // log(1000/16)
#define NMS_THR 0.7f

typedef unsigned long long u64;

// ---------------- device-global scratch (no runtime allocation) ----------------
__device__ unsigned int       g_sb[NIMG][NANC];            // sigmoid score bits, anchor order
__device__ float4             g_boxes[NIMG][PRE];
__device__ float              g_scores[NIMG][PRE];
__device__ unsigned char      g_valid[NIMG][PREP];         // padded: lanes read 64B each
__device__ u64                g_mask[NIMG][PRE][NWRD];     // ~4.1 MB

// =============================================================================
// Kernel 0: full-chip sigmoid + layout transform (N,A,H,W) -> [img][hw*3+a]
// =============================================================================
__global__ __launch_bounds__(256)
void sigmoid_kernel(const float* __restrict__ obj_all)
{
    int gid = blockIdx.x * 256 + threadIdx.x;
    if (gid >= NIMG * NANC) return;
    int img = gid / NANC;
    int r   = gid - img * NANC;      // r = a*NHW + hw  (input memory order -> coalesced read)
    int a   = r / NHW;
    int hw  = r - a * NHW;
    float o = obj_all[gid];
    float s = 1.0f / (1.0f + expf(-o));
    g_sb[img][hw * NA + a] = __float_as_uint(s);   // scores in (0,1): bits monotonic
}

// =============================================================================
// Kernel A: radix-select threshold -> compact -> bitonic sort -> decode/clip.
// One block (1024 thr) per image.
// =============================================================================
__global__ __launch_bounds__(1024)
void topk_decode_kernel(const float* __restrict__ reg_all,
                        const float* __restrict__ anc_all)
{
    extern __shared__ unsigned char smem_raw[];
    unsigned int* s_sb   = (unsigned int*)smem_raw;                  // 30000 u32
    u64*          s_keys = (u64*)(smem_raw + 120000);                // 2048 u64

    __shared__ unsigned int s_hist[256];
    __shared__ unsigned int s_scan[256];
    __shared__ unsigned int s_cnt;
    __shared__ unsigned int s_prefix;
    __shared__ int          s_K;

    const int img = blockIdx.x;
    const int tid = threadIdx.x;

    // ---- phase 1: coalesced vector copy of score bits into smem ----
    {
        const uint4* src = (const uint4*)g_sb[img];          // 7500 uint4
        uint4* dst = (uint4*)s_sb;
        for (int i = tid; i < NANC / 4; i += 1024) dst[i] = src[i];
    }
    if (tid == 0) { s_prefix = 0; s_K = PRE; }
    __syncthreads();

    // ---- phase 2: 4-pass MSB radix select for the PRE-th largest value ----
    unsigned int pmask = 0;
    for (int pass = 0; pass < 4; ++pass) {
        int shift = 24 - 8 * pass;
        if (tid < 256) s_hist[tid] = 0;
        __syncthreads();
        unsigned int prefix = s_prefix;
        for (int i = tid; i < NANC; i += 1024) {
            unsigned int v = s_sb[i];
            if ((v & pmask) == prefix)
                atomicAdd(&s_hist[(v >> shift) & 255u], 1u);
        }
        __syncthreads();
        // parallel inclusive suffix-sum over 256 bins
        if (tid < 256) s_scan[tid] = s_hist[tid];
        __syncthreads();
        for (int off = 1; off < 256; off <<= 1) {
            unsigned int add = 0;
            if (tid < 256) add = (tid + off < 256) ? s_scan[tid + off] : 0u;
            __syncthreads();
            if (tid < 256) s_scan[tid] += add;
            __syncthreads();
        }
        int Kc = s_K;
        __syncthreads();
        if (tid < 256) {
            unsigned int cs  = s_scan[tid];
            unsigned int nxt = (tid < 255) ? s_scan[tid + 1] : 0u;
            if ((int)cs >= Kc && (int)nxt < Kc) {
                s_K = Kc - (int)nxt;                       // remaining within this bin
                s_prefix = s_prefix | ((unsigned int)tid << shift);
            }
        }
        pmask |= (0xFFu << shift);
        __syncthreads();
    }
    const unsigned int T = s_prefix;   // exact bits of the PRE-th largest score

    // ---- phase 3: compact candidates >= T ----
    if (tid == 0) s_cnt = 0;
    __syncthreads();
    for (int i = tid; i < NANC; i += 1024) {
        unsigned int v = s_sb[i];
        if (v >= T) {
            unsigned int pos = atomicAdd(&s_cnt, 1u);
            if (pos < PREP)
                s_keys[pos] = ((u64)v << 32) | (u64)(~(unsigned int)i);
        }
    }
    __syncthreads();
    unsigned int n = s_cnt; if (n > PREP) n = PREP;
    for (int i = tid; i < PREP; i += 1024)
        if (i >= (int)n) s_keys[i] = 0ULL;
    __syncthreads();

    // ---- phase 4: bitonic sort (descending) of 2048 keys ----
    for (int k = 2; k <= PREP; k <<= 1) {
        for (int j = k >> 1; j > 0; j >>= 1) {
            for (int i = tid; i < PREP; i += 1024) {
                int l = i ^ j;
                if (l > i) {
                    u64 a = s_keys[i];
                    u64 b = s_keys[l];
                    bool up = ((i & k) == 0);
                    if ((a < b) == up) { s_keys[i] = b; s_keys[l] = a; }
                }
            }
            __syncthreads();
        }
    }

    // ---- phase 5: decode / clip / validity for top PRE ----
    const float* reg = reg_all + (size_t)img * NA * 4 * NHW;
    const float4* anc = (const float4*)anc_all + (size_t)img * NANC;
    for (int j = tid; j < PRE; j += 1024) {
        u64 key = s_keys[j];
        unsigned int idx = ~(unsigned int)(key & 0xFFFFFFFFull);
        float score = __uint_as_float((unsigned int)(key >> 32));

        int hw = idx / NA;
        int a  = idx - hw * NA;
        const float* rb = reg + (a * 4) * NHW + hw;
        float dx = rb[0];
        float dy = rb[NHW];
        float dw = rb[2 * NHW];
        float dh = rb[3 * NHW];
        dw = fminf(dw, BBOX_CLIP);
        dh = fminf(dh, BBOX_CLIP);

        float4 A4 = anc[idx];
        float w  = A4.z - A4.x + 1.0f;
        float h  = A4.w - A4.y + 1.0f;
        float cx = A4.x + 0.5f * w;
        float cy = A4.y + 0.5f * h;

        float pcx = dx * w + cx;
        float pcy = dy * h + cy;
        float pw  = expf(dw) * w;
        float ph  = expf(dh) * h;

        float x1 = pcx - 0.5f * pw;
        float y1 = pcy - 0.5f * ph;
        float x2 = pcx + 0.5f * pw - 1.0f;
        float y2 = pcy + 0.5f * ph - 1.0f;

        x1 = fminf(fmaxf(x1, 0.0f), IMGW - 1.0f);
        x2 = fminf(fmaxf(x2, 0.0f), IMGW - 1.0f);
        y1 = fminf(fmaxf(y1, 0.0f), IMGW - 1.0f);
        y2 = fminf(fmaxf(y2, 0.0f), IMGW - 1.0f);

        float ws = x2 - x1 + 1.0f;
        float hs = y2 - y1 + 1.0f;
        float xc = x1 + ws * 0.5f;
        float yc = y1 + hs * 0.5f;
        unsigned char v = (ws >= 0.0f) & (hs >= 0.0f) & (xc < IMGW) & (yc < IMGW);

        g_boxes[img][j]  = make_float4(x1, y1, x2, y2);
        g_scores[img][j] = score;
        g_valid[img][j]  = v;
    }
    // zero the pad bytes so kernel C's packed reads are well-defined
    for (int j = PRE + tid; j < PREP; j += 1024) g_valid[img][j] = 0;
}

// =============================================================================
// Kernel B: NMS suppression bitmask. grid (colBlk=32, rowQuad=8, img=8), 256 thr
// =============================================================================
__global__ __launch_bounds__(256)
void nms_mask_kernel()
{
    const int img    = blockIdx.z;
    const int colBlk = blockIdx.x;
    const int row    = blockIdx.y * 256 + threadIdx.x;

    __shared__ float4 s_col[64];
    const int colBase = colBlk * 64;
    if (threadIdx.x < 64) {
        int c = colBase + threadIdx.x;
        if (c < PRE) s_col[threadIdx.x] = g_boxes[img][c];
    }
    __syncthreads();

    if (row >= PRE) return;
    if (colBlk < (row >> 6)) {             // tile entirely below diagonal
        g_mask[img][row][colBlk] = 0ULL;
        return;
    }

    float4 rb = g_boxes[img][row];
    float rArea = (rb.z - rb.x + 1.0f) * (rb.w - rb.y + 1.0f);
    u64 bits = 0ULL;
    int nCols = PRE - colBase; if (nCols > 64) nCols = 64;

    for (int jj = 0; jj < nCols; ++jj) {
        int col = colBase + jj;
        if (col <= row) continue;
        float4 cb = s_col[jj];
        float xx1 = fmaxf(rb.x, cb.x);
        float yy1 = fmaxf(rb.y, cb.y);
        float xx2 = fminf(rb.z, cb.z);
        float yy2 = fminf(rb.w, cb.w);
        float iw = fmaxf(xx2 - xx1 + 1.0f, 0.0f);
        float ih = fmaxf(yy2 - yy1 + 1.0f, 0.0f);
        float inter = iw * ih;
        float cArea = (cb.z - cb.x + 1.0f) * (cb.w - cb.y + 1.0f);
        float iou = inter / (rArea + cArea - inter);
        if (iou > NMS_THR) bits |= (1ULL << jj);
    }
    g_mask[img][row][colBlk] = bits;
}

// =============================================================================
// Kernel C: greedy scan via double-buffered SMEM tiles. 256 threads/image.
//   warps 1..7 : copy tile t+1 (64 rows x 32 words = 16KB) gmem -> smem
//   warp 0     : scan tile t from smem; per candidate j (row r=t*64+j):
//                  m  = tile[j][lane]   (LDS, off serial chain)
//                  ms = tile[j][t]      (uniform LDS broadcast -- replaces SHFL)
//                  kept = !(cur & bit); cur |= kept?ms:0; rw |= kept?m:0
//                  record: unconditional STS (trash slot when !kept or k>=POST)
//   1 shfl + 1 __syncthreads per tile; uniform early exit at tile boundaries.
// Output layout: boxes[8*1000*4] | scores[8*1000] | valid[8*1000]  (float32)
// =============================================================================
__global__ __launch_bounds__(256)
void nms_reduce_kernel(float* __restrict__ out)
{
    const int img  = blockIdx.x;
    const int tid  = threadIdx.x;
    const int lane = tid & 31;
    const int wid  = tid >> 5;

    __shared__ u64 s_tile[2][64][NWRD];      // 32 KB double-buffered mask tile
    __shared__ int s_kept[POST + 1];         // slot POST = trash (never read)
    __shared__ int s_kdone;

    float* outB = out;                       // (8,1000,4)
    float* outS = out + NIMG * POST * 4;     // (8,1000)
    float* outV = out + NIMG * POST * 5;     // (8,1000)

    // zero outputs (all threads; fast)
    for (int i = tid; i < POST * 4; i += 256) outB[img * POST * 4 + i] = 0.0f;
    for (int i = tid; i < POST;     i += 256) {
        outS[img * POST + i] = 0.0f;
        outV[img * POST + i] = 0.0f;
    }
    if (tid == 0) s_kdone = 0;

    // preload tile 0 (all threads)
    {
        const u64* src = &g_mask[img][0][0];
        for (int i = tid; i < 64 * NWRD; i += 256)
            s_tile[0][0][i] = src[i];        // rows 0..63 fully in range
    }

    // scanner warp state: removed-word per lane, seeded by ~valid
    u64 rw = 0ULL;
    if (wid == 0) {
        const u64* vp = (const u64*)g_valid[img];
        u64 bits = 0ULL;
        #pragma unroll
        for (int q = 0; q < 8; ++q) {
            u64 v8 = vp[lane * 8 + q];
            #pragma unroll
            for (int b = 0; b < 8; ++b)
                if ((v8 >> (8 * b)) & 0xFFull) bits |= 1ULL << (q * 8 + b);
        }
        rw = ~bits;
    }
    __syncthreads();

    int k = 0;
    for (int t = 0; t < NTILE; ++t) {
        if (wid >= 1) {
            // loaders: fill the other buffer with tile t+1 (zero-fill OOB rows)
            const int t1 = t + 1;
            if (t1 < NTILE) {
                const int r0 = t1 * 64;
                const int nval = (PRE - r0 < 64 ? PRE - r0 : 64) * NWRD;
                const u64* src = &g_mask[img][r0][0];
                u64* dst = &s_tile[t1 & 1][0][0];
                for (int i = tid - 32; i < 64 * NWRD; i += 224)
                    dst[i] = (i < nval) ? src[i] : 0ULL;
            }
        } else {
            // scanner: walk 64 candidates of tile t
            const u64 (*tp)[NWRD] = s_tile[t & 1];
            u64 cur = __shfl_sync(0xFFFFFFFFu, rw, t);   // word t state
            #pragma unroll 1
            for (int g = 0; g < 8; ++g) {                // 8 groups of 8
                const int j0 = g * 8;
                // batched LDS (off the serial chain)
                u64 m[8], ms[8];
                #pragma unroll
                for (int j = 0; j < 8; ++j) {
                    m[j]  = tp[j0 + j][lane];
                    ms[j] = tp[j0 + j][t];               // uniform broadcast
                }
                // pure-ALU serial chain + unconditional recording
                const int base = t * 64 + j0;
                #pragma unroll
                for (int j = 0; j < 8; ++j) {
                    const u64 bitj = 1ULL << (j0 + j);
                    const bool kept = (cur & bitj) == 0ULL;
                    cur |= kept ? ms[j] : 0ULL;
                    rw  |= kept ? m[j]  : 0ULL;
                    const int kk = (kept && k < POST) ? k : POST;
                    s_kept[kk] = base + j;               // uniform addr+value
                    k += (int)kept;
                }
            }
            if (lane == 0) s_kdone = k;
        }
        __syncthreads();
        if (s_kdone >= POST) break;          // uniform across the block
    }

    const int nk = (s_kdone < POST) ? s_kdone : POST;
    for (int j = tid; j < nk; j += 256) {
        int i = s_kept[j];
        float4 b = g_boxes[img][i];
        ((float4*)outB)[img * POST + j] = b;
        outS[img * POST + j] = g_scores[img][i];
        outV[img * POST + j] = 1.0f;
    }
}

// =============================================================================
extern "C" void kernel_launch(void* const* d_in, const int* in_sizes, int n_in,
                              void* d_out, int out_size)
{
    const float* obj = (const float*)d_in[0];   // (8,3,100,100)
    const float* reg = (const float*)d_in[1];   // (8,12,100,100)
    const float* anc = (const float*)d_in[2];   // (8,30000,4)
    float* out = (float*)d_out;
    (void)in_sizes; (void)n_in; (void)out_size;

    const int smemA = 120000 + PREP * 8;        // 136384 bytes dynamic
    cudaFuncSetAttribute(topk_decode_kernel,
                         cudaFuncAttributeMaxDynamicSharedMemorySize, smemA);

    sigmoid_kernel<<<(NIMG * NANC + 255) / 256, 256>>>(obj);
    topk_decode_kernel<<<NIMG, 1024, smemA>>>(reg, anc);
    dim3 gB(NWRD, 8, NIMG);
    nms_mask_kernel<<<gB, 256>>>();
    nms_reduce_kernel<<<NIMG, 256>>>(out);
}

// round 11
// speedup vs baseline: 2.1747x; 1.0315x over previous
#include <cuda_runtime.h>
#include <cuda_bf16.h>
#include <cstdint>

#define NIMG 8
#define NA   3
#define HH   100
#define WW   100
#define NHW  10000
#define NANC 30000          // H*W*A
#define PRE  2000
#define PREP 2048           // padded to pow2 for bitonic sort
#define POST 1000
#define NWRD 32             // ceil(2000/64) mask words per row
#define NTILE 32            // 64-row tiles
#define IMGW 1600.0f
#define BBOX_CLIP 4.135166556742356f   // log(1000/16)
#define NMS_THR 0.7f

typedef unsigned long long u64;
typedef unsigned int       u32;

// ---------------- device-global scratch (no runtime allocation) ----------------
__device__ float4             g_boxes[NIMG][PRE];
__device__ float              g_scores[NIMG][PRE];
__device__ unsigned char      g_valid[NIMG][PREP];         // padded: lanes read 64B each
__device__ u64                g_mask[NIMG][PRE][NWRD];     // ~4.1 MB

// =============================================================================
// Kernel A: sigmoid -> radix-select threshold -> compact -> bitonic sort ->
//           decode/clip.  One block (1024 thr) per image.
// =============================================================================
__global__ __launch_bounds__(1024)
void topk_decode_kernel(const float* __restrict__ obj_all,
                        const float* __restrict__ reg_all,
                        const float* __restrict__ anc_all)
{
    extern __shared__ unsigned char smem_raw[];
    u32* s_sb   = (u32*)smem_raw;                  // 30000 u32
    u64* s_keys = (u64*)(smem_raw + 120000);       // 2048 u64

    __shared__ u32 s_hist[256];
    __shared__ u32 s_cnt;
    __shared__ u32 s_prefix;
    __shared__ int s_K;

    const int img = blockIdx.x;
    const int tid = threadIdx.x;

    // ---- phase 1: sigmoid + transpose into smem (coalesced read; stride-3
    //      word smem store is bank-conflict-free since gcd(3,32)=1) ----
    {
        const float* obj = obj_all + (size_t)img * NANC;   // layout a*NHW + hw
        for (int i = tid; i < NANC; i += 1024) {
            int a  = i / NHW;
            int hw = i - a * NHW;
            float o = obj[i];
            float s = 1.0f / (1.0f + expf(-o));
            s_sb[hw * NA + a] = __float_as_uint(s);        // (0,1): bits monotonic
        }
    }
    if (tid == 0) { s_prefix = 0; s_K = PRE; }
    __syncthreads();

    // ---- phase 2: 4-pass MSB radix select for the PRE-th largest value ----
    u32 pmask = 0;
    for (int pass = 0; pass < 4; ++pass) {
        int shift = 24 - 8 * pass;
        if (tid < 256) s_hist[tid] = 0;
        __syncthreads();
        u32 prefix = s_prefix;
        for (int i = tid; i < NANC; i += 1024) {
            u32 v = s_sb[i];
            if ((v & pmask) == prefix)
                atomicAdd(&s_hist[(v >> shift) & 255u], 1u);
        }
        __syncthreads();
        // warp 0: shfl-based suffix scan over 256 bins (no barrier loop)
        if (tid < 32) {
            const int lane = tid;
            u32 h[8];
            u32 chunk = 0;
            #pragma unroll
            for (int j = 0; j < 8; ++j) { h[j] = s_hist[lane * 8 + j]; chunk += h[j]; }
            // inclusive suffix over lanes: s_incl(L) = sum chunks[L..31]
            u32 s_incl = chunk;
            #pragma unroll
            for (int off = 1; off < 32; off <<= 1) {
                u32 t = __shfl_down_sync(0xFFFFFFFFu, s_incl, off);
                if (lane + off < 32) s_incl += t;
            }
            const u32 s_excl = s_incl - chunk;  // sum chunks (L..31] i.e. > L
            // in-lane suffix over the 8 owned bins (descending j)
            const int Kc = s_K;
            u32 suf = s_excl;                   // S[bin 8L+8]
            #pragma unroll
            for (int j = 7; j >= 0; --j) {
                u32 nxt = suf;                  // S[bin+1]
                suf += h[j];                    // S[bin]
                if ((int)suf >= Kc && (int)nxt < Kc) {
                    s_K = Kc - (int)nxt;
                    s_prefix = prefix | ((u32)(lane * 8 + j) << shift);
                }
            }
        }
        pmask |= (0xFFu << shift);
        __syncthreads();
    }
    const u32 T = s_prefix;   // exact bits of the PRE-th largest score

    // ---- phase 3: compact candidates >= T ----
    if (tid == 0) s_cnt = 0;
    __syncthreads();
    for (int i = tid; i < NANC; i += 1024) {
        u32 v = s_sb[i];
        if (v >= T) {
            u32 pos = atomicAdd(&s_cnt, 1u);
            if (pos < PREP)
                s_keys[pos] = ((u64)v << 32) | (u64)(~(u32)i);
        }
    }
    __syncthreads();
    u32 n = s_cnt; if (n > PREP) n = PREP;
    for (int i = tid; i < PREP; i += 1024)
        if (i >= (int)n) s_keys[i] = 0ULL;
    __syncthreads();

    // ---- phase 4: bitonic sort (descending) of 2048 keys ----
    for (int k = 2; k <= PREP; k <<= 1) {
        for (int j = k >> 1; j > 0; j >>= 1) {
            for (int i = tid; i < PREP; i += 1024) {
                int l = i ^ j;
                if (l > i) {
                    u64 a = s_keys[i];
                    u64 b = s_keys[l];
                    bool up = ((i & k) == 0);
                    if ((a < b) == up) { s_keys[i] = b; s_keys[l] = a; }
                }
            }
            __syncthreads();
        }
    }

    // ---- phase 5: decode / clip / validity for top PRE ----
    const float* reg = reg_all + (size_t)img * NA * 4 * NHW;
    const float4* anc = (const float4*)anc_all + (size_t)img * NANC;
    for (int j = tid; j < PRE; j += 1024) {
        u64 key = s_keys[j];
        u32 idx = ~(u32)(key & 0xFFFFFFFFull);
        float score = __uint_as_float((u32)(key >> 32));

        int hw = idx / NA;
        int a  = idx - hw * NA;
        const float* rb = reg + (a * 4) * NHW + hw;
        float dx = rb[0];
        float dy = rb[NHW];
        float dw = rb[2 * NHW];
        float dh = rb[3 * NHW];
        dw = fminf(dw, BBOX_CLIP);
        dh = fminf(dh, BBOX_CLIP);

        float4 A4 = anc[idx];
        float w  = A4.z - A4.x + 1.0f;
        float h  = A4.w - A4.y + 1.0f;
        float cx = A4.x + 0.5f * w;
        float cy = A4.y + 0.5f * h;

        float pcx = dx * w + cx;
        float pcy = dy * h + cy;
        float pw  = expf(dw) * w;
        float ph  = expf(dh) * h;

        float x1 = pcx - 0.5f * pw;
        float y1 = pcy - 0.5f * ph;
        float x2 = pcx + 0.5f * pw - 1.0f;
        float y2 = pcy + 0.5f * ph - 1.0f;

        x1 = fminf(fmaxf(x1, 0.0f), IMGW - 1.0f);
        x2 = fminf(fmaxf(x2, 0.0f), IMGW - 1.0f);
        y1 = fminf(fmaxf(y1, 0.0f), IMGW - 1.0f);
        y2 = fminf(fmaxf(y2, 0.0f), IMGW - 1.0f);

        float ws = x2 - x1 + 1.0f;
        float hs = y2 - y1 + 1.0f;
        float xc = x1 + ws * 0.5f;
        float yc = y1 + hs * 0.5f;
        unsigned char v = (ws >= 0.0f) & (hs >= 0.0f) & (xc < IMGW) & (yc < IMGW);

        g_boxes[img][j]  = make_float4(x1, y1, x2, y2);
        g_scores[img][j] = score;
        g_valid[img][j]  = v;
    }
    // zero the pad bytes so kernel C's packed reads are well-defined
    for (int j = PRE + tid; j < PREP; j += 1024) g_valid[img][j] = 0;
}

// =============================================================================
// Kernel B: NMS suppression bitmask. grid (colBlk=32, rowQuad=8, img=8), 256 thr
// =============================================================================
__global__ __launch_bounds__(256)
void nms_mask_kernel()
{
    const int img    = blockIdx.z;
    const int colBlk = blockIdx.x;
    const int row    = blockIdx.y * 256 + threadIdx.x;

    __shared__ float4 s_col[64];
    const int colBase = colBlk * 64;
    if (threadIdx.x < 64) {
        int c = colBase + threadIdx.x;
        if (c < PRE) s_col[threadIdx.x] = g_boxes[img][c];
    }
    __syncthreads();

    if (row >= PRE) return;
    if (colBlk < (row >> 6)) {             // tile entirely below diagonal
        g_mask[img][row][colBlk] = 0ULL;
        return;
    }

    float4 rb = g_boxes[img][row];
    float rArea = (rb.z - rb.x + 1.0f) * (rb.w - rb.y + 1.0f);
    u64 bits = 0ULL;
    int nCols = PRE - colBase; if (nCols > 64) nCols = 64;

    for (int jj = 0; jj < nCols; ++jj) {
        int col = colBase + jj;
        if (col <= row) continue;
        float4 cb = s_col[jj];
        float xx1 = fmaxf(rb.x, cb.x);
        float yy1 = fmaxf(rb.y, cb.y);
        float xx2 = fminf(rb.z, cb.z);
        float yy2 = fminf(rb.w, cb.w);
        float iw = fmaxf(xx2 - xx1 + 1.0f, 0.0f);
        float ih = fmaxf(yy2 - yy1 + 1.0f, 0.0f);
        float inter = iw * ih;
        float cArea = (cb.z - cb.x + 1.0f) * (cb.w - cb.y + 1.0f);
        float iou = inter / (rArea + cArea - inter);
        if (iou > NMS_THR) bits |= (1ULL << jj);
    }
    g_mask[img][row][colBlk] = bits;
}

// =============================================================================
// Kernel C: greedy scan via double-buffered SMEM tiles. 256 threads/image.
//   warps 1..7 : copy tile t+1 (64 rows x 32 words = 16KB) gmem -> smem
//   warp 0     : scan tile t; per candidate only ALU:
//                  kept = !(cur & bit); cur|=kept?ms:0; rw|=kept?m:0;
//                  keptw|=kept?bit:0          (NO per-candidate store)
//                per tile: popc + __fns emit of kept indices by all 32 lanes
//   1 shfl + 1 __syncthreads per tile; uniform early exit at tile boundaries.
// Output layout: boxes[8*1000*4] | scores[8*1000] | valid[8*1000]  (float32)
// =============================================================================
__global__ __launch_bounds__(256)
void nms_reduce_kernel(float* __restrict__ out)
{
    const int img  = blockIdx.x;
    const int tid  = threadIdx.x;
    const int lane = tid & 31;
    const int wid  = tid >> 5;

    __shared__ u64 s_tile[2][64][NWRD];      // 32 KB double-buffered mask tile
    __shared__ int s_kept[POST];
    __shared__ int s_kdone;

    float* outB = out;                       // (8,1000,4)
    float* outS = out + NIMG * POST * 4;     // (8,1000)
    float* outV = out + NIMG * POST * 5;     // (8,1000)

    // zero outputs (all threads; fast)
    for (int i = tid; i < POST * 4; i += 256) outB[img * POST * 4 + i] = 0.0f;
    for (int i = tid; i < POST;     i += 256) {
        outS[img * POST + i] = 0.0f;
        outV[img * POST + i] = 0.0f;
    }
    if (tid == 0) s_kdone = 0;

    // preload tile 0 (all threads)
    {
        const u64* src = &g_mask[img][0][0];
        for (int i = tid; i < 64 * NWRD; i += 256)
            s_tile[0][0][i] = src[i];        // rows 0..63 fully in range
    }

    // scanner warp state: removed-word per lane, seeded by ~valid
    u64 rw = 0ULL;
    if (wid == 0) {
        const u64* vp = (const u64*)g_valid[img];
        u64 bits = 0ULL;
        #pragma unroll
        for (int q = 0; q < 8; ++q) {
            u64 v8 = vp[lane * 8 + q];
            #pragma unroll
            for (int b = 0; b < 8; ++b)
                if ((v8 >> (8 * b)) & 0xFFull) bits |= 1ULL << (q * 8 + b);
        }
        rw = ~bits;
    }
    __syncthreads();

    int k = 0;
    for (int t = 0; t < NTILE; ++t) {
        if (wid >= 1) {
            // loaders: fill the other buffer with tile t+1 (zero-fill OOB rows)
            const int t1 = t + 1;
            if (t1 < NTILE) {
                const int r0 = t1 * 64;
                const int nval = (PRE - r0 < 64 ? PRE - r0 : 64) * NWRD;
                const u64* src = &g_mask[img][r0][0];
                u64* dst = &s_tile[t1 & 1][0][0];
                for (int i = tid - 32; i < 64 * NWRD; i += 224)
                    dst[i] = (i < nval) ? src[i] : 0ULL;
            }
        } else {
            // scanner: walk 64 candidates of tile t, record keeps in a bitmask
            const u64 (*tp)[NWRD] = s_tile[t & 1];
            u64 cur = __shfl_sync(0xFFFFFFFFu, rw, t);   // word t state
            u64 keptw = 0ULL;
            #pragma unroll 1
            for (int g = 0; g < 8; ++g) {                // 8 groups of 8
                const int j0 = g * 8;
                // batched LDS (off the serial chain)
                u64 m[8], ms[8];
                #pragma unroll
                for (int j = 0; j < 8; ++j) {
                    m[j]  = tp[j0 + j][lane];
                    ms[j] = tp[j0 + j][t];               // uniform broadcast
                }
                // pure-ALU serial chain, zero stores
                #pragma unroll
                for (int j = 0; j < 8; ++j) {
                    const u64 bitj = 1ULL << (j0 + j);
                    const bool kept = (cur & bitj) == 0ULL;
                    cur   |= kept ? ms[j] : 0ULL;
                    rw    |= kept ? m[j]  : 0ULL;
                    keptw |= kept ? bitj  : 0ULL;
                }
            }
            // per-tile emit: lanes extract kept indices from the bitmask
            const u32 lo = (u32)keptw, hi = (u32)(keptw >> 32);
            const int nlo = __popc(lo);
            const int ncnt = nlo + __popc(hi);
            #pragma unroll
            for (int r = 0; r < 2; ++r) {
                const int idx = lane + r * 32;
                if (idx < ncnt && k + idx < POST) {
                    int pos = (idx < nlo) ? __fns(lo, 0, idx + 1)
                                          : 32 + __fns(hi, 0, idx - nlo + 1);
                    s_kept[k + idx] = t * 64 + pos;
                }
            }
            k += ncnt;
            if (lane == 0) s_kdone = k;
        }
        __syncthreads();
        if (s_kdone >= POST) break;          // uniform across the block
    }

    const int nk = (s_kdone < POST) ? s_kdone : POST;
    for (int j = tid; j < nk; j += 256) {
        int i = s_kept[j];
        float4 b = g_boxes[img][i];
        ((float4*)outB)[img * POST + j] = b;
        outS[img * POST + j] = g_scores[img][i];
        outV[img * POST + j] = 1.0f;
    }
}

// =============================================================================
extern "C" void kernel_launch(void* const* d_in, const int* in_sizes, int n_in,
                              void* d_out, int out_size)
{
    const float* obj = (const float*)d_in[0];   // (8,3,100,100)
    const float* reg = (const float*)d_in[1];   // (8,12,100,100)
    const float* anc = (const float*)d_in[2];   // (8,30000,4)
    float* out = (float*)d_out;
    (void)in_sizes; (void)n_in; (void)out_size;

    const int smemA = 120000 + PREP * 8;        // 136384 bytes dynamic
    cudaFuncSetAttribute(topk_decode_kernel,
                         cudaFuncAttributeMaxDynamicSharedMemorySize, smemA);

    topk_decode_kernel<<<NIMG, 1024, smemA>>>(obj, reg, anc);
    dim3 gB(NWRD, 8, NIMG);
    nms_mask_kernel<<<gB, 256>>>();
    nms_reduce_kernel<<<NIMG, 256>>>(out);
}